// round 14
// baseline (speedup 1.0000x reference)
#include <cuda_runtime.h>
#include <cuda_bf16.h>
#include <cstdint>

// Problem dims
#define B     64
#define T     512
#define DIN   512
#define H1    1024
#define H2    1024
#define DOUT  256

#define NCTA  148
#define NTHR  256
#define GSTRIDE (NCTA*NTHR)

// ---------------------------------------------------------------------------
// Device global scratch (no runtime allocation allowed)
// ---------------------------------------------------------------------------
__device__ float g_U[T * H1 * B];        // x@W_in^T + b_in + b_h1, layout [t][j][b]
__device__ float g_xT[T * DIN * B];      // x transposed: [(t*DIN+k)][b]
__device__ float g_WT_in[DIN * H1];      // [k][j]
__device__ float g_WT_h1[H1 * H1];       // [i][j]
__device__ float g_WT_cat[2 * H1 * H2];  // rows 0..H1-1: W_12^T ; rows H1..: W_h2^T  [i][j]
__device__ float g_WT_out[H2 * DOUT];    // [i][j2]
__device__ float g_sCat[2 * H1 * B];     // spikes [i][b]; first H1 rows = s1, next H1 = s2
__device__ float g_v1[H1 * B];           // [j][b]
__device__ float g_v2[H2 * B];
__device__ float g_acc[DOUT * B];        // [j2][b]
__device__ float g_PA[16 * H1 * B];      // split-K partials: layer1 GEMM
__device__ float g_PB[32 * H2 * B];      // layer2 fused GEMM (K=2048)
__device__ float g_PC[16 * DOUT * B];    // readout GEMM

__device__ unsigned g_bar_cnt;
__device__ volatile unsigned g_bar_gen;

// ---------------------------------------------------------------------------
// Grid-wide barrier (all NCTA CTAs co-resident; counters zeroed by init kernel)
// ---------------------------------------------------------------------------
__device__ __forceinline__ void grid_sync()
{
    __syncthreads();
    if (threadIdx.x == 0) {
        __threadfence();
        unsigned my  = atomicAdd(&g_bar_cnt, 1u);
        unsigned gen = my / NCTA;
        if ((my % NCTA) == (NCTA - 1)) {
            g_bar_gen = gen + 1;
        } else {
            while (g_bar_gen < gen + 1) { /* spin on L2 line */ }
        }
        __threadfence();
    }
    __syncthreads();
}

// ---------------------------------------------------------------------------
// Shared-memory tile GEMM: out-tile = 64(b) x 128(j), K-chunk = 64.
// S: [64 k][64 b] rows contiguous (stride 64).  Wp: [64 k][ldw], cols 0..127 used.
// 256 threads, micro-tile 4b x 8j per thread, accumulates into acc[8][4].
// ---------------------------------------------------------------------------
template <bool SCG>
__device__ __forceinline__ void tile_fill_compute(const float* __restrict__ S,
                                                  const float* __restrict__ Wp,
                                                  int ldw,
                                                  float* sSh, float* wSh,
                                                  float (&acc)[8][4])
{
    const int tid = threadIdx.x;
    __syncthreads();  // protect shared buffers from previous tile's readers

    // Fill sSh: 64x64 floats = 1024 float4
#pragma unroll
    for (int i = 0; i < 4; i++) {
        int idx = tid + i * 256;
        int k = idx >> 4;
        int c = (idx & 15) << 2;
        const float4* p = (const float4*)(S + k * 64 + c);
        float4 v = SCG ? __ldcg(p) : __ldg(p);
        *(float4*)(sSh + k * 64 + c) = v;
    }
    // Fill wSh: 64x128 floats = 2048 float4
#pragma unroll
    for (int i = 0; i < 8; i++) {
        int idx = tid + i * 256;
        int k = idx >> 5;
        int c = (idx & 31) << 2;
        float4 v = __ldg((const float4*)(Wp + k * ldw + c));
        *(float4*)(wSh + k * 128 + c) = v;
    }
    __syncthreads();

    const int bq = tid & 15;       // 16 groups of 4 b
    const int jq = tid >> 4;       // 16 groups of 8 j
    const float4* s4 = (const float4*)sSh;
    const float4* w4 = (const float4*)wSh;

#pragma unroll 8
    for (int k = 0; k < 64; k++) {
        float4 sv = s4[k * 16 + bq];
        float4 w0 = w4[k * 32 + jq * 2];
        float4 w1 = w4[k * 32 + jq * 2 + 1];
        float sb[4] = { sv.x, sv.y, sv.z, sv.w };
        float wj[8] = { w0.x, w0.y, w0.z, w0.w, w1.x, w1.y, w1.z, w1.w };
#pragma unroll
        for (int jj = 0; jj < 8; jj++)
#pragma unroll
            for (int bb = 0; bb < 4; bb++)
                acc[jj][bb] = fmaf(wj[jj], sb[bb], acc[jj][bb]);
    }
}

__device__ __forceinline__ void tile_store(float* __restrict__ dst, float (&acc)[8][4])
{
    const int bq = threadIdx.x & 15;
    const int jq = threadIdx.x >> 4;
#pragma unroll
    for (int jj = 0; jj < 8; jj++) {
        float4 o = make_float4(acc[jj][0], acc[jj][1], acc[jj][2], acc[jj][3]);
        *(float4*)(dst + (jq * 8 + jj) * B + bq * 4) = o;
    }
}

// ---------------------------------------------------------------------------
// Init: zero barrier state
// ---------------------------------------------------------------------------
__global__ void init_kernel()
{
    if (threadIdx.x == 0) {
        g_bar_cnt = 0u;
        g_bar_gen = 0u;
    }
}

// ---------------------------------------------------------------------------
// Generic 32x32 tiled transpose: out[x*R + y] = in[y*C + x]
// launch: grid(C/32, R/32), block(32, 8)
// ---------------------------------------------------------------------------
__global__ void transpose32(const float* __restrict__ in, float* __restrict__ out,
                            int R, int C)
{
    __shared__ float tile[32][33];
    int cb = blockIdx.x * 32;
    int rb = blockIdx.y * 32;
    int x = cb + threadIdx.x;
#pragma unroll
    for (int i = threadIdx.y; i < 32; i += 8) {
        int y = rb + i;
        if (y < R && x < C) tile[i][threadIdx.x] = in[(long)y * C + x];
    }
    __syncthreads();
    int xo = rb + threadIdx.x;
#pragma unroll
    for (int i = threadIdx.y; i < 32; i += 8) {
        int yo = cb + i;
        if (yo < C && xo < R) out[(long)yo * R + xo] = tile[threadIdx.x][i];
    }
}

// ---------------------------------------------------------------------------
// U precompute: U[t][j][b] = sum_k x[b][t][k]*W_in[j][k] + b_in[j] + b_h1[j]
// grid = T * 8 jt-tiles = 4096 blocks
// ---------------------------------------------------------------------------
__global__ void __launch_bounds__(NTHR, 2) u_kernel(const float* __restrict__ bin,
                                                    const float* __restrict__ bh1)
{
    __shared__ float sSh[64 * 64];
    __shared__ float wSh[64 * 128];
    const int t  = blockIdx.x >> 3;
    const int jt = blockIdx.x & 7;

    float acc[8][4];
#pragma unroll
    for (int jj = 0; jj < 8; jj++)
#pragma unroll
        for (int bb = 0; bb < 4; bb++) acc[jj][bb] = 0.f;

    for (int kc = 0; kc < 8; kc++) {
        tile_fill_compute<false>(g_xT + (t * DIN + kc * 64) * B,
                                 g_WT_in + kc * 64 * H1 + jt * 128,
                                 H1, sSh, wSh, acc);
    }

    const int bq = threadIdx.x & 15;
    const int jq = threadIdx.x >> 4;
#pragma unroll
    for (int jj = 0; jj < 8; jj++) {
        int j = jt * 128 + jq * 8 + jj;
        float bias = __ldg(bin + j) + __ldg(bh1 + j);
        float4 o = make_float4(acc[jj][0] + bias, acc[jj][1] + bias,
                               acc[jj][2] + bias, acc[jj][3] + bias);
        *(float4*)(g_U + t * (H1 * B) + j * B + bq * 4) = o;
    }
}

// ---------------------------------------------------------------------------
// Persistent recurrent kernel: 512 timesteps x 4 phases, grid barriers.
// Phase1: layer1 GEMM partials (s1_{t-1}@W_h1^T) + readout partials (s2_{t-1}@W_out^T)
// Phase2: reduce + U[t] -> LIF1 -> s1_t ; reduce readout -> acc
// Phase3: fused layer2 GEMM partials ([s1_t, s2_{t-1}] @ [W_12;W_h2]^T, K=2048)
// Phase4: reduce + biases -> LIF2 -> s2_t
// ---------------------------------------------------------------------------
__global__ void __launch_bounds__(NTHR, 1) srnn_kernel(const float* __restrict__ b12,
                                                       const float* __restrict__ bh2,
                                                       const float* __restrict__ bout,
                                                       float* __restrict__ dout)
{
    __shared__ float sSh[64 * 64];
    __shared__ float wSh[64 * 128];
    const int tid  = threadIdx.x;
    const int gtid = blockIdx.x * NTHR + tid;

    // Phase 0: zero recurrent state (device globals persist across launches)
    for (int i = gtid; i < 2 * H1 * B; i += GSTRIDE) g_sCat[i] = 0.f;
    for (int i = gtid; i < H1 * B;     i += GSTRIDE) g_v1[i]  = 0.f;
    for (int i = gtid; i < H2 * B;     i += GSTRIDE) g_v2[i]  = 0.f;
    for (int i = gtid; i < DOUT * B;   i += GSTRIDE) g_acc[i] = 0.f;
    grid_sync();

    for (int t = 0; t < T; t++) {
        // ---- Phase 1: layer1 partials (128 tiles) + readout partials (32 tiles) ----
        for (int w = blockIdx.x; w < 160; w += NCTA) {
            float acc[8][4];
#pragma unroll
            for (int jj = 0; jj < 8; jj++)
#pragma unroll
                for (int bb = 0; bb < 4; bb++) acc[jj][bb] = 0.f;

            if (w < 128) {
                int jt = w >> 4, kc = w & 15;
                tile_fill_compute<true>(g_sCat + kc * 64 * B,
                                        g_WT_h1 + kc * 64 * H1 + jt * 128,
                                        H1, sSh, wSh, acc);
                tile_store(g_PA + kc * (H1 * B) + jt * 128 * B, acc);
            } else {
                int u = w - 128;
                int jt = u >> 4, kc = u & 15;   // jt in {0,1}, kc in 0..15
                tile_fill_compute<true>(g_sCat + H1 * B + kc * 64 * B,
                                        g_WT_out + kc * 64 * DOUT + jt * 128,
                                        DOUT, sSh, wSh, acc);
                tile_store(g_PC + kc * (DOUT * B) + jt * 128 * B, acc);
            }
        }
        grid_sync();

        // ---- Phase 2: reduce + LIF1 ; readout accumulate (contribution of s2_{t-1}) ----
        {
            const float* Ut = g_U + t * (H1 * B);
            for (int i = gtid; i < H1 * B; i += GSTRIDE) {
                float sum = __ldg(Ut + i);
#pragma unroll
                for (int kc = 0; kc < 16; kc++) sum += __ldcg(g_PA + kc * (H1 * B) + i);
                float v = 0.9f * g_v1[i] + sum;
                float s = (v >= 1.0f) ? 1.0f : 0.0f;
                g_v1[i]   = v - s;
                g_sCat[i] = s;
            }
            for (int i = gtid; i < DOUT * B; i += GSTRIDE) {
                float sum = 0.f;
#pragma unroll
                for (int kc = 0; kc < 16; kc++) sum += __ldcg(g_PC + kc * (DOUT * B) + i);
                g_acc[i] += sum;
            }
        }
        grid_sync();

        // ---- Phase 3: fused layer-2 GEMM partials (256 tiles, K=2048) ----
        for (int w = blockIdx.x; w < 256; w += NCTA) {
            int jt = w >> 5, kc = w & 31;
            float acc[8][4];
#pragma unroll
            for (int jj = 0; jj < 8; jj++)
#pragma unroll
                for (int bb = 0; bb < 4; bb++) acc[jj][bb] = 0.f;
            tile_fill_compute<true>(g_sCat + kc * 64 * B,
                                    g_WT_cat + kc * 64 * H2 + jt * 128,
                                    H2, sSh, wSh, acc);
            tile_store(g_PB + kc * (H2 * B) + jt * 128 * B, acc);
        }
        grid_sync();

        // ---- Phase 4: reduce + biases -> LIF2 -> s2_t ----
        for (int i = gtid; i < H2 * B; i += GSTRIDE) {
            int j = i >> 6;
            float sum = __ldg(b12 + j) + __ldg(bh2 + j);
#pragma unroll
            for (int kc = 0; kc < 32; kc++) sum += __ldcg(g_PB + kc * (H2 * B) + i);
            float v = 0.9f * g_v2[i] + sum;
            float s = (v >= 1.0f) ? 1.0f : 0.0f;
            g_v2[i]            = v - s;
            g_sCat[H1 * B + i] = s;
        }
        grid_sync();
    }

    // ---- Final readout contribution from s2_{T-1} ----
    for (int w = blockIdx.x; w < 32; w += NCTA) {
        int jt = w >> 4, kc = w & 15;
        float acc[8][4];
#pragma unroll
        for (int jj = 0; jj < 8; jj++)
#pragma unroll
            for (int bb = 0; bb < 4; bb++) acc[jj][bb] = 0.f;
        tile_fill_compute<true>(g_sCat + H1 * B + kc * 64 * B,
                                g_WT_out + kc * 64 * DOUT + jt * 128,
                                DOUT, sSh, wSh, acc);
        tile_store(g_PC + kc * (DOUT * B) + jt * 128 * B, acc);
    }
    grid_sync();

    for (int i = gtid; i < DOUT * B; i += GSTRIDE) {
        float sum = 0.f;
#pragma unroll
        for (int kc = 0; kc < 16; kc++) sum += __ldcg(g_PC + kc * (DOUT * B) + i);
        int j = i >> 6;
        int b = i & 63;
        dout[b * DOUT + j] = g_acc[i] + sum + 512.0f * __ldg(bout + j);
    }
}

// ---------------------------------------------------------------------------
// Host launcher
// ---------------------------------------------------------------------------
extern "C" void kernel_launch(void* const* d_in, const int* in_sizes, int n_in,
                              void* d_out, int out_size)
{
    const float* x     = (const float*)d_in[0];
    const float* W_in  = (const float*)d_in[1];
    const float* b_in  = (const float*)d_in[2];
    const float* W_h1  = (const float*)d_in[3];
    const float* b_h1  = (const float*)d_in[4];
    const float* W_12  = (const float*)d_in[5];
    const float* b_12  = (const float*)d_in[6];
    const float* W_h2  = (const float*)d_in[7];
    const float* b_h2  = (const float*)d_in[8];
    const float* W_out = (const float*)d_in[9];
    const float* b_out = (const float*)d_in[10];
    float* out = (float*)d_out;

    float *p_xT, *p_WT_in, *p_WT_h1, *p_WT_cat, *p_WT_out;
    cudaGetSymbolAddress((void**)&p_xT,     g_xT);
    cudaGetSymbolAddress((void**)&p_WT_in,  g_WT_in);
    cudaGetSymbolAddress((void**)&p_WT_h1,  g_WT_h1);
    cudaGetSymbolAddress((void**)&p_WT_cat, g_WT_cat);
    cudaGetSymbolAddress((void**)&p_WT_out, g_WT_out);

    init_kernel<<<1, 32>>>();

    dim3 tb(32, 8);
    // x [B=64, T*DIN=262144] -> xT [T*DIN, 64]
    transpose32<<<dim3(8192, 2), tb>>>(x, p_xT, 64, T * DIN);
    // W_in [H1=1024, DIN=512] -> WT_in [512, 1024]
    transpose32<<<dim3(16, 32), tb>>>(W_in, p_WT_in, H1, DIN);
    // W_h1 [1024, 1024] -> WT_h1
    transpose32<<<dim3(32, 32), tb>>>(W_h1, p_WT_h1, H1, H1);
    // W_12 [H2, H1] -> WT_cat rows [0, H1)
    transpose32<<<dim3(32, 32), tb>>>(W_12, p_WT_cat, H2, H1);
    // W_h2 [H2, H2] -> WT_cat rows [H1, 2*H1)
    transpose32<<<dim3(32, 32), tb>>>(W_h2, p_WT_cat + H1 * H2, H2, H2);
    // W_out [DOUT=256, H2=1024] -> WT_out [1024, 256]
    transpose32<<<dim3(32, 8), tb>>>(W_out, p_WT_out, DOUT, H2);

    // Precompute U for all timesteps
    u_kernel<<<T * 8, NTHR>>>(b_in, b_h1);

    // Persistent sequential scan
    srnn_kernel<<<NCTA, NTHR>>>(b_12, b_h2, b_out, out);
}

// round 15
// speedup vs baseline: 1.2751x; 1.2751x over previous
#include <cuda_runtime.h>
#include <cuda_bf16.h>
#include <cstdint>

// Problem dims
#define B     64
#define T     512
#define DIN   512
#define H1    1024
#define H2    1024
#define DOUT  256

#define NCTA  148
#define NTHR  256
#define GSTRIDE (NCTA*NTHR)

// ---------------------------------------------------------------------------
// Device global scratch (no runtime allocation allowed)
// ---------------------------------------------------------------------------
__device__ float g_U[T * H1 * B];        // x@W_in^T + b_in + b_h1, [t][j][b]
__device__ float g_xT[T * DIN * B];      // x transposed: [(t*DIN+k)][b]
__device__ float g_WT_in[DIN * H1];      // [k][j]
__device__ float g_WT_h1[H1 * H1];       // [i][j]
__device__ float g_WT_cat[2 * H1 * H2];  // rows 0..H1-1: W_12^T ; rows H1..: W_h2^T
__device__ float g_WT_out[H2 * DOUT];    // [i][j2]
__device__ float g_sCat[2 * H1 * B];     // spikes [i][b]; first H1 rows = s1, next = s2
__device__ float g_v1[H1 * B];
__device__ float g_v2[H2 * B];
__device__ float g_acc[DOUT * B];
__device__ float g_PA[8  * H1 * B];      // layer1 partials   (8 slabs, 128-K each)
__device__ float g_PBh2[8 * H2 * B];     // s2@W_h2 partials  (8 slabs)
__device__ float g_PB12[16 * H2 * B];    // s1@W_12 partials  (16 slabs, 64-K each)
__device__ float g_PC[8  * DOUT * B];    // readout partials  (8 slabs)

__device__ unsigned g_bar_cnt;
__device__ volatile unsigned g_bar_gen;

// ---------------------------------------------------------------------------
// Grid-wide barrier
// ---------------------------------------------------------------------------
__device__ __forceinline__ void grid_sync()
{
    __syncthreads();
    if (threadIdx.x == 0) {
        __threadfence();
        unsigned my  = atomicAdd(&g_bar_cnt, 1u);
        unsigned gen = my / NCTA;
        if ((my % NCTA) == (NCTA - 1)) {
            g_bar_gen = gen + 1;
        } else {
            while (g_bar_gen < gen + 1) { }
        }
        __threadfence();
    }
    __syncthreads();
}

// ---------------------------------------------------------------------------
// cp.async helpers (16B, .cg = L2 only -> coherent wrt other CTAs' stores)
// ---------------------------------------------------------------------------
__device__ __forceinline__ unsigned smem_u32(const void* p)
{
    return (unsigned)__cvta_generic_to_shared(p);
}
__device__ __forceinline__ void cpasync16(unsigned dst, const void* src)
{
    asm volatile("cp.async.cg.shared.global [%0], [%1], 16;" :: "r"(dst), "l"(src));
}
#define CP_COMMIT()  asm volatile("cp.async.commit_group;")
#define CP_WAIT(n)   asm volatile("cp.async.wait_group %0;" :: "n"(n))

// Fill S chunk: 64 k x 64 b (16 KB). Each thread: 4x16B.
__device__ __forceinline__ void fill_S_async(float* sSh, const float* __restrict__ S)
{
    const int tid = threadIdx.x;
#pragma unroll
    for (int i = 0; i < 4; i++) {
        int idx = tid + i * 256;
        int k = idx >> 4;
        int c = (idx & 15) << 2;
        cpasync16(smem_u32(sSh + k * 64 + c), S + k * 64 + c);
    }
}
// Fill W chunk: 64 k x 128 j (32 KB). Each thread: 8x16B.
__device__ __forceinline__ void fill_W_async(float* wSh, const float* __restrict__ W, int ldw)
{
    const int tid = threadIdx.x;
#pragma unroll
    for (int i = 0; i < 8; i++) {
        int idx = tid + i * 256;
        int k = idx >> 5;
        int c = (idx & 31) << 2;
        cpasync16(smem_u32(wSh + k * 128 + c), W + k * ldw + c);
    }
}

// 64x128x64 micro-kernel: 4b x 8j per thread
__device__ __forceinline__ void mm_compute(const float* __restrict__ sSh,
                                           const float* __restrict__ wSh,
                                           float (&acc)[8][4])
{
    const int bq = threadIdx.x & 15;
    const int jq = threadIdx.x >> 4;
    const float4* s4 = (const float4*)sSh;
    const float4* w4 = (const float4*)wSh;
#pragma unroll 8
    for (int k = 0; k < 64; k++) {
        float4 sv = s4[k * 16 + bq];
        float4 w0 = w4[k * 32 + jq * 2];
        float4 w1 = w4[k * 32 + jq * 2 + 1];
        float sb[4] = { sv.x, sv.y, sv.z, sv.w };
        float wj[8] = { w0.x, w0.y, w0.z, w0.w, w1.x, w1.y, w1.z, w1.w };
#pragma unroll
        for (int jj = 0; jj < 8; jj++)
#pragma unroll
            for (int bb = 0; bb < 4; bb++)
                acc[jj][bb] = fmaf(wj[jj], sb[bb], acc[jj][bb]);
    }
}

__device__ __forceinline__ void tile_store(float* __restrict__ dst, float (&acc)[8][4])
{
    const int bq = threadIdx.x & 15;
    const int jq = threadIdx.x >> 4;
#pragma unroll
    for (int jj = 0; jj < 8; jj++) {
        float4 o = make_float4(acc[jj][0], acc[jj][1], acc[jj][2], acc[jj][3]);
        *(float4*)(dst + (jq * 8 + jj) * B + bq * 4) = o;
    }
}

__device__ __forceinline__ void acc_zero(float (&acc)[8][4])
{
#pragma unroll
    for (int jj = 0; jj < 8; jj++)
#pragma unroll
        for (int bb = 0; bb < 4; bb++) acc[jj][bb] = 0.f;
}

// ---------------------------------------------------------------------------
// Legacy static-smem tile routine (used by u_kernel only)
// ---------------------------------------------------------------------------
__device__ __forceinline__ void tile_fill_compute_sync(const float* __restrict__ S,
                                                       const float* __restrict__ Wp,
                                                       int ldw,
                                                       float* sSh, float* wSh,
                                                       float (&acc)[8][4])
{
    const int tid = threadIdx.x;
    __syncthreads();
#pragma unroll
    for (int i = 0; i < 4; i++) {
        int idx = tid + i * 256;
        int k = idx >> 4;
        int c = (idx & 15) << 2;
        *(float4*)(sSh + k * 64 + c) = __ldg((const float4*)(S + k * 64 + c));
    }
#pragma unroll
    for (int i = 0; i < 8; i++) {
        int idx = tid + i * 256;
        int k = idx >> 5;
        int c = (idx & 31) << 2;
        *(float4*)(wSh + k * 128 + c) = __ldg((const float4*)(Wp + k * ldw + c));
    }
    __syncthreads();
    mm_compute(sSh, wSh, acc);
}

// ---------------------------------------------------------------------------
__global__ void init_kernel()
{
    if (threadIdx.x == 0) { g_bar_cnt = 0u; g_bar_gen = 0u; }
}

// 32x32 tiled transpose: out[x*R + y] = in[y*C + x]; grid(C/32, R/32), block(32,8)
__global__ void transpose32(const float* __restrict__ in, float* __restrict__ out,
                            int R, int C)
{
    __shared__ float tile[32][33];
    int cb = blockIdx.x * 32;
    int rb = blockIdx.y * 32;
    int x = cb + threadIdx.x;
#pragma unroll
    for (int i = threadIdx.y; i < 32; i += 8) {
        int y = rb + i;
        if (y < R && x < C) tile[i][threadIdx.x] = in[(long)y * C + x];
    }
    __syncthreads();
    int xo = rb + threadIdx.x;
#pragma unroll
    for (int i = threadIdx.y; i < 32; i += 8) {
        int yo = cb + i;
        if (yo < C && xo < R) out[(long)yo * R + xo] = tile[threadIdx.x][i];
    }
}

// U precompute: U[t][j][b] = sum_k x[b][t][k]*W_in[j][k] + b_in[j] + b_h1[j]
__global__ void __launch_bounds__(NTHR, 2) u_kernel(const float* __restrict__ bin,
                                                    const float* __restrict__ bh1)
{
    __shared__ float sSh[64 * 64];
    __shared__ float wSh[64 * 128];
    const int t  = blockIdx.x >> 3;
    const int jt = blockIdx.x & 7;

    float acc[8][4];
    acc_zero(acc);
    for (int kc = 0; kc < 8; kc++) {
        tile_fill_compute_sync(g_xT + (t * DIN + kc * 64) * B,
                               g_WT_in + kc * 64 * H1 + jt * 128,
                               H1, sSh, wSh, acc);
    }
    const int bq = threadIdx.x & 15;
    const int jq = threadIdx.x >> 4;
#pragma unroll
    for (int jj = 0; jj < 8; jj++) {
        int j = jt * 128 + jq * 8 + jj;
        float bias = __ldg(bin + j) + __ldg(bh1 + j);
        float4 o = make_float4(acc[jj][0] + bias, acc[jj][1] + bias,
                               acc[jj][2] + bias, acc[jj][3] + bias);
        *(float4*)(g_U + (size_t)t * (H1 * B) + j * B + bq * 4) = o;
    }
}

// ---------------------------------------------------------------------------
// Persistent recurrent kernel, 96 KB dynamic smem (two 48 KB chunk buffers).
// Per step:
//  P1 (144 uniform 2-chunk tiles, one wave):
//      layer1: s1_{t-1}@W_h1^T  (64 tiles)  -> g_PA   (8 slabs)
//      h2-rec: s2_{t-1}@W_h2^T  (64 tiles)  -> g_PBh2 (8 slabs)   [moved from P3]
//      readout: s2_{t-1}@W_out^T (16 tiles) -> g_PC   (8 slabs)
//  P2: reduce PA + U -> LIF1 -> s1_t ; reduce PC -> acc
//  P3 (128 single-chunk tiles, one wave): s1_t@W_12^T -> g_PB12 (16 slabs)
//  P4: reduce PBh2+PB12 + biases -> LIF2 -> s2_t
// Weight fills for the next phase are issued BEFORE the preceding barrier.
// ---------------------------------------------------------------------------
__global__ void __launch_bounds__(NTHR, 1) srnn_kernel(const float* __restrict__ b12,
                                                       const float* __restrict__ bh2,
                                                       const float* __restrict__ bout,
                                                       float* __restrict__ dout)
{
    extern __shared__ float dsm[];
    float* s0buf = dsm;               // 4096 floats
    float* w0buf = dsm + 4096;        // 8192 floats
    float* s1buf = dsm + 12288;       // 4096 floats
    float* w1buf = dsm + 16384;       // 8192 floats

    const int c    = blockIdx.x;
    const int tid  = threadIdx.x;
    const int gtid = c * NTHR + tid;

    // ---- static tile assignment for P1 (144 tiles, 2 chunks of 64-K each) ----
    const bool p1_act = (c < 144);
    const float *p1_S0 = nullptr, *p1_S1 = nullptr, *p1_W0 = nullptr, *p1_W1 = nullptr;
    float* p1_dst = nullptr;
    int p1_ldw = H1;
    if (p1_act) {
        if (c < 64) {                      // layer1: s1 @ W_h1^T
            int jt = c >> 3, kc = c & 7;
            int r0 = kc * 128, r1 = r0 + 64;
            p1_S0 = g_sCat + r0 * B;  p1_S1 = g_sCat + r1 * B;
            p1_W0 = g_WT_h1 + r0 * H1 + jt * 128;
            p1_W1 = g_WT_h1 + r1 * H1 + jt * 128;
            p1_ldw = H1;
            p1_dst = g_PA + kc * (H1 * B) + jt * 128 * B;
        } else if (c < 128) {              // s2 @ W_h2^T
            int u = c - 64;
            int jt = u >> 3, kc = u & 7;
            int r0 = kc * 128, r1 = r0 + 64;
            p1_S0 = g_sCat + H1 * B + r0 * B;  p1_S1 = g_sCat + H1 * B + r1 * B;
            p1_W0 = g_WT_cat + H1 * H2 + r0 * H2 + jt * 128;
            p1_W1 = g_WT_cat + H1 * H2 + r1 * H2 + jt * 128;
            p1_ldw = H2;
            p1_dst = g_PBh2 + kc * (H2 * B) + jt * 128 * B;
        } else {                           // readout: s2 @ W_out^T
            int u = c - 128;
            int jt = u >> 3, kc = u & 7;   // jt in {0,1}
            int r0 = kc * 128, r1 = r0 + 64;
            p1_S0 = g_sCat + H1 * B + r0 * B;  p1_S1 = g_sCat + H1 * B + r1 * B;
            p1_W0 = g_WT_out + r0 * DOUT + jt * 128;
            p1_W1 = g_WT_out + r1 * DOUT + jt * 128;
            p1_ldw = DOUT;
            p1_dst = g_PC + kc * (DOUT * B) + jt * 128 * B;
        }
    }
    // ---- P3 tile (128 single-chunk tiles) ----
    const bool p3_act = (c < 128);
    const float *p3_S = nullptr, *p3_W = nullptr;
    float* p3_dst = nullptr;
    if (p3_act) {
        int jt = c >> 4, kc = c & 15;
        int r = kc * 64;
        p3_S = g_sCat + r * B;                     // s1
        p3_W = g_WT_cat + r * H2 + jt * 128;       // W_12^T rows
        p3_dst = g_PB12 + kc * (H2 * B) + jt * 128 * B;
    }

    // ---- zero recurrent state ----
    for (int i = gtid; i < 2 * H1 * B; i += GSTRIDE) g_sCat[i] = 0.f;
    for (int i = gtid; i < H1 * B;     i += GSTRIDE) g_v1[i]  = 0.f;
    for (int i = gtid; i < H2 * B;     i += GSTRIDE) g_v2[i]  = 0.f;
    for (int i = gtid; i < DOUT * B;   i += GSTRIDE) g_acc[i] = 0.f;

    // prefetch P1 weights (chunk 0) behind the first barrier
    if (p1_act) { fill_W_async(w0buf, p1_W0, p1_ldw); CP_COMMIT(); }
    grid_sync();

    for (int t = 0; t < T; t++) {
        // ---- Phase 1 ----
        if (p1_act) {
            fill_S_async(s0buf, p1_S0); CP_COMMIT();
            fill_W_async(w1buf, p1_W1, p1_ldw);
            fill_S_async(s1buf, p1_S1); CP_COMMIT();
            float acc[8][4];
            acc_zero(acc);
            CP_WAIT(1); __syncthreads();
            mm_compute(s0buf, w0buf, acc);
            CP_WAIT(0); __syncthreads();
            mm_compute(s1buf, w1buf, acc);
            tile_store(p1_dst, acc);
        }
        grid_sync();

        // ---- Phase 2: reduce + LIF1 ; readout accumulate ----
        {
            const int i4 = gtid;
            if (i4 < (H1 * B) / 4) {
                const float4* Ut4 = (const float4*)(g_U + (size_t)t * (H1 * B));
                float4 sum = __ldg(Ut4 + i4);
#pragma unroll
                for (int kc = 0; kc < 8; kc++) {
                    float4 p = __ldcg((const float4*)g_PA + kc * (H1 * B / 4) + i4);
                    sum.x += p.x; sum.y += p.y; sum.z += p.z; sum.w += p.w;
                }
                float4 v = *((float4*)g_v1 + i4);
                float4 s;
                v.x = 0.9f * v.x + sum.x; s.x = (v.x >= 1.f) ? 1.f : 0.f; v.x -= s.x;
                v.y = 0.9f * v.y + sum.y; s.y = (v.y >= 1.f) ? 1.f : 0.f; v.y -= s.y;
                v.z = 0.9f * v.z + sum.z; s.z = (v.z >= 1.f) ? 1.f : 0.f; v.z -= s.z;
                v.w = 0.9f * v.w + sum.w; s.w = (v.w >= 1.f) ? 1.f : 0.f; v.w -= s.w;
                *((float4*)g_v1 + i4)   = v;
                *((float4*)g_sCat + i4) = s;
            }
            if (i4 < (DOUT * B) / 4) {
                float4 sum = make_float4(0.f, 0.f, 0.f, 0.f);
#pragma unroll
                for (int kc = 0; kc < 8; kc++) {
                    float4 p = __ldcg((const float4*)g_PC + kc * (DOUT * B / 4) + i4);
                    sum.x += p.x; sum.y += p.y; sum.z += p.z; sum.w += p.w;
                }
                float4 a = *((float4*)g_acc + i4);
                a.x += sum.x; a.y += sum.y; a.z += sum.z; a.w += sum.w;
                *((float4*)g_acc + i4) = a;
            }
        }
        // prefetch P3 weights behind the barrier
        if (p3_act) { fill_W_async(w0buf, p3_W, H2); CP_COMMIT(); }
        grid_sync();

        // ---- Phase 3: s1 @ W_12^T ----
        if (p3_act) {
            fill_S_async(s0buf, p3_S); CP_COMMIT();
            float acc[8][4];
            acc_zero(acc);
            CP_WAIT(0); __syncthreads();
            mm_compute(s0buf, w0buf, acc);
            tile_store(p3_dst, acc);
        }
        grid_sync();

        // ---- Phase 4: reduce + biases -> LIF2 -> s2 ----
        {
            const int i4 = gtid;
            if (i4 < (H2 * B) / 4) {
                int j = i4 >> 4;
                float bias = __ldg(b12 + j) + __ldg(bh2 + j);
                float4 sum = make_float4(bias, bias, bias, bias);
#pragma unroll
                for (int kc = 0; kc < 8; kc++) {
                    float4 p = __ldcg((const float4*)g_PBh2 + kc * (H2 * B / 4) + i4);
                    sum.x += p.x; sum.y += p.y; sum.z += p.z; sum.w += p.w;
                }
#pragma unroll
                for (int kc = 0; kc < 16; kc++) {
                    float4 p = __ldcg((const float4*)g_PB12 + kc * (H2 * B / 4) + i4);
                    sum.x += p.x; sum.y += p.y; sum.z += p.z; sum.w += p.w;
                }
                float4 v = *((float4*)g_v2 + i4);
                float4 s;
                v.x = 0.9f * v.x + sum.x; s.x = (v.x >= 1.f) ? 1.f : 0.f; v.x -= s.x;
                v.y = 0.9f * v.y + sum.y; s.y = (v.y >= 1.f) ? 1.f : 0.f; v.y -= s.y;
                v.z = 0.9f * v.z + sum.z; s.z = (v.z >= 1.f) ? 1.f : 0.f; v.z -= s.z;
                v.w = 0.9f * v.w + sum.w; s.w = (v.w >= 1.f) ? 1.f : 0.f; v.w -= s.w;
                *((float4*)g_v2 + i4)                  = v;
                *((float4*)g_sCat + (H1 * B / 4) + i4) = s;
            }
        }
        // prefetch next step's P1 weights behind the barrier
        if (t + 1 < T && p1_act) { fill_W_async(w0buf, p1_W0, p1_ldw); CP_COMMIT(); }
        grid_sync();
    }

    // ---- Final readout contribution from s2_{T-1} (16 two-chunk tiles) ----
    if (c < 16) {
        int jt = c >> 3, kc = c & 7;
        int r0 = kc * 128, r1 = r0 + 64;
        const float* S0 = g_sCat + H1 * B + r0 * B;
        const float* S1 = g_sCat + H1 * B + r1 * B;
        const float* W0 = g_WT_out + r0 * DOUT + jt * 128;
        const float* W1 = g_WT_out + r1 * DOUT + jt * 128;
        fill_W_async(w0buf, W0, DOUT); fill_S_async(s0buf, S0); CP_COMMIT();
        fill_W_async(w1buf, W1, DOUT); fill_S_async(s1buf, S1); CP_COMMIT();
        float acc[8][4];
        acc_zero(acc);
        CP_WAIT(1); __syncthreads();
        mm_compute(s0buf, w0buf, acc);
        CP_WAIT(0); __syncthreads();
        mm_compute(s1buf, w1buf, acc);
        tile_store(g_PC + kc * (DOUT * B) + jt * 128 * B, acc);
    }
    grid_sync();

    for (int i = gtid; i < DOUT * B; i += GSTRIDE) {
        float sum = 0.f;
#pragma unroll
        for (int kc = 0; kc < 8; kc++) sum += __ldcg(g_PC + kc * (DOUT * B) + i);
        int j = i >> 6;
        int b = i & 63;
        dout[b * DOUT + j] = __ldcg(g_acc + i) + sum + 512.0f * __ldg(bout + j);
    }
}

// ---------------------------------------------------------------------------
// Host launcher
// ---------------------------------------------------------------------------
extern "C" void kernel_launch(void* const* d_in, const int* in_sizes, int n_in,
                              void* d_out, int out_size)
{
    const float* x     = (const float*)d_in[0];
    const float* W_in  = (const float*)d_in[1];
    const float* b_in  = (const float*)d_in[2];
    const float* W_h1  = (const float*)d_in[3];
    const float* b_h1  = (const float*)d_in[4];
    const float* W_12  = (const float*)d_in[5];
    const float* b_12  = (const float*)d_in[6];
    const float* W_h2  = (const float*)d_in[7];
    const float* b_h2  = (const float*)d_in[8];
    const float* W_out = (const float*)d_in[9];
    const float* b_out = (const float*)d_in[10];
    float* out = (float*)d_out;

    float *p_xT, *p_WT_in, *p_WT_h1, *p_WT_cat, *p_WT_out;
    cudaGetSymbolAddress((void**)&p_xT,     g_xT);
    cudaGetSymbolAddress((void**)&p_WT_in,  g_WT_in);
    cudaGetSymbolAddress((void**)&p_WT_h1,  g_WT_h1);
    cudaGetSymbolAddress((void**)&p_WT_cat, g_WT_cat);
    cudaGetSymbolAddress((void**)&p_WT_out, g_WT_out);

    cudaFuncSetAttribute(srnn_kernel, cudaFuncAttributeMaxDynamicSharedMemorySize,
                         98304);

    init_kernel<<<1, 32>>>();

    dim3 tb(32, 8);
    // x [B=64, T*DIN] -> xT [T*DIN, 64]
    transpose32<<<dim3(8192, 2), tb>>>(x, p_xT, 64, T * DIN);
    // W_in [H1, DIN] -> WT_in [DIN, H1]
    transpose32<<<dim3(16, 32), tb>>>(W_in, p_WT_in, H1, DIN);
    // W_h1 [H1, H1] -> WT_h1
    transpose32<<<dim3(32, 32), tb>>>(W_h1, p_WT_h1, H1, H1);
    // W_12 [H2, H1] -> WT_cat rows [0, H1)
    transpose32<<<dim3(32, 32), tb>>>(W_12, p_WT_cat, H2, H1);
    // W_h2 [H2, H2] -> WT_cat rows [H1, 2*H1)
    transpose32<<<dim3(32, 32), tb>>>(W_h2, p_WT_cat + H1 * H2, H2, H2);
    // W_out [DOUT, H2] -> WT_out [H2, DOUT]
    transpose32<<<dim3(32, 8), tb>>>(W_out, p_WT_out, DOUT, H2);

    // Precompute U for all timesteps
    u_kernel<<<T * 8, NTHR>>>(b_in, b_h1);

    // Persistent sequential scan
    srnn_kernel<<<NCTA, NTHR, 98304>>>(b_12, b_h2, b_out, out);
}

// round 17
// speedup vs baseline: 1.5185x; 1.1909x over previous
#include <cuda_runtime.h>
#include <cuda_bf16.h>
#include <cstdint>

// Problem dims
#define B     64
#define T     512
#define DIN   512
#define H1    1024
#define H2    1024
#define DOUT  256
#define KDIM  1024

#define NCTA  148
#define NTHR  256
#define GSTRIDE (NCTA*NTHR)

// ---------------------------------------------------------------------------
// Device global scratch
// ---------------------------------------------------------------------------
__device__ float g_U[T * H1 * B];        // x@W_in^T + b_in + b_h1, [t][j][b]
__device__ float g_xT[T * DIN * B];      // x transposed
__device__ float g_WT_in[DIN * H1];      // [k][j] for u_kernel

// bf16x3 weight splits, layout [split][j][k] (j rows, k contiguous, ld = 1024)
__device__ __nv_bfloat16 g_Wh1s [3 * H1   * KDIM];
__device__ __nv_bfloat16 g_Wh2s [3 * H2   * KDIM];
__device__ __nv_bfloat16 g_W12s [3 * H2   * KDIM];
__device__ __nv_bfloat16 g_Wouts[3 * DOUT * KDIM];

// spikes in bf16, [b][k] (k contiguous) -- B operand for mma row.col
__device__ __nv_bfloat16 g_sT1[B * H1];
__device__ __nv_bfloat16 g_sT2[B * H2];

__device__ float g_v1[H1 * B];
__device__ float g_v2[H2 * B];
__device__ float g_acc[DOUT * B];
__device__ float g_PA  [8  * H1 * B];    // layer1 partials  (8 slabs)
__device__ float g_PBh2[8  * H2 * B];    // s2@W_h2 partials (8 slabs)
__device__ float g_PB12[16 * H2 * B];    // s1@W_12 partials (16 slabs)
__device__ float g_PC  [8  * DOUT * B];  // readout partials (8 slabs)

__device__ unsigned g_bar_cnt;
__device__ volatile unsigned g_bar_gen;

// ---------------------------------------------------------------------------
// Grid-wide barrier
// ---------------------------------------------------------------------------
__device__ __forceinline__ void grid_sync()
{
    __syncthreads();
    if (threadIdx.x == 0) {
        __threadfence();
        unsigned my  = atomicAdd(&g_bar_cnt, 1u);
        unsigned gen = my / NCTA;
        if ((my % NCTA) == (NCTA - 1)) {
            g_bar_gen = gen + 1;
        } else {
            while (g_bar_gen < gen + 1) { }
        }
        __threadfence();
    }
    __syncthreads();
}

// ---------------------------------------------------------------------------
// cp.async helpers (.cg = L2 path, coherent wrt other CTAs' stores)
// ---------------------------------------------------------------------------
__device__ __forceinline__ unsigned smem_u32(const void* p)
{
    return (unsigned)__cvta_generic_to_shared(p);
}
__device__ __forceinline__ void cpasync16(unsigned dst, const void* src)
{
    asm volatile("cp.async.cg.shared.global [%0], [%1], 16;" :: "r"(dst), "l"(src));
}
#define CP_COMMIT()  asm volatile("cp.async.commit_group;")
#define CP_WAIT(n)   asm volatile("cp.async.wait_group %0;" :: "n"(n))

#define SWZ(o) ((o) ^ (((o) >> 3) & 0x70))

// ---------------------------------------------------------------------------
// mma primitives
// ---------------------------------------------------------------------------
__device__ __forceinline__ void ldsm_x4(uint32_t (&r)[4], unsigned addr)
{
    asm volatile("ldmatrix.sync.aligned.m8n8.x4.shared.b16 {%0,%1,%2,%3}, [%4];"
        : "=r"(r[0]), "=r"(r[1]), "=r"(r[2]), "=r"(r[3]) : "r"(addr));
}
__device__ __forceinline__ void ldsm_x2(uint32_t (&r)[2], unsigned addr)
{
    asm volatile("ldmatrix.sync.aligned.m8n8.x2.shared.b16 {%0,%1}, [%2];"
        : "=r"(r[0]), "=r"(r[1]) : "r"(addr));
}
__device__ __forceinline__ void mma_bf16(float (&c)[4], const uint32_t (&a)[4],
                                         const uint32_t (&b)[2])
{
    asm volatile("mma.sync.aligned.m16n8k16.row.col.f32.bf16.bf16.f32 "
        "{%0,%1,%2,%3}, {%4,%5,%6,%7}, {%8,%9}, {%0,%1,%2,%3};"
        : "+f"(c[0]), "+f"(c[1]), "+f"(c[2]), "+f"(c[3])
        : "r"(a[0]), "r"(a[1]), "r"(a[2]), "r"(a[3]), "r"(b[0]), "r"(b[1]));
}

// ---------------------------------------------------------------------------
// Tile engine: CTA tile = 128 j x 64 b, chunk = 64 k.
// A smem: 128 rows x 128B (64 bf16), SW128-swizzled.  B smem: 64 rows x 128B.
// 8 warps: wm = wid&1 (2 x 64 j), wn = wid>>1 (4 x 16 b).
// Per warp: 4 m-tiles(16) x 2 n-tiles(8), acc[4][2][4] fp32.
// ---------------------------------------------------------------------------
#define STAGE_BYTES 24576    // 16KB A + 8KB B
#define A_OFF 0
#define B_OFF 16384

__device__ __forceinline__ void fillA_async(unsigned sbase, const __nv_bfloat16* __restrict__ src)
{
    const int tid = threadIdx.x;
#pragma unroll
    for (int i = 0; i < 4; i++) {
        int idx = tid + i * 256;           // 0..1023
        int row = idx >> 3, seg = idx & 7;
        int off = row * 128 + seg * 16;
        cpasync16(sbase + SWZ(off), src + (size_t)row * KDIM + seg * 8);
    }
}
__device__ __forceinline__ void fillB_async(unsigned sbase, const __nv_bfloat16* __restrict__ src)
{
    const int tid = threadIdx.x;
#pragma unroll
    for (int i = 0; i < 2; i++) {
        int idx = tid + i * 256;           // 0..511
        int row = idx >> 3, seg = idx & 7;
        int off = row * 128 + seg * 16;
        cpasync16(sbase + SWZ(off), src + (size_t)row * KDIM + seg * 8);
    }
}

__device__ __forceinline__ void mma_chunk(unsigned Abase, unsigned Bbase,
                                          float (&acc)[4][2][4])
{
    const int lane = threadIdx.x & 31;
    const int wid  = threadIdx.x >> 5;
    const int wm = wid & 1, wn = wid >> 1;
    const int arow = wm * 64 + (lane & 15);
    const int acb  = ((lane >> 4) << 4);          // 0 or 16 bytes
    const int brow = wn * 16 + (lane & 7);
    const int bcb  = (((lane >> 3) & 1) << 4);
#pragma unroll
    for (int ks = 0; ks < 4; ks++) {
        uint32_t a[4][4];
#pragma unroll
        for (int mt = 0; mt < 4; mt++) {
            int off = (arow + mt * 16) * 128 + ks * 32 + acb;
            ldsm_x4(a[mt], Abase + SWZ(off));
        }
        uint32_t bf[2][2];
#pragma unroll
        for (int nt = 0; nt < 2; nt++) {
            int off = (brow + nt * 8) * 128 + ks * 32 + bcb;
            ldsm_x2(bf[nt], Bbase + SWZ(off));
        }
#pragma unroll
        for (int mt = 0; mt < 4; mt++)
#pragma unroll
            for (int nt = 0; nt < 2; nt++)
                mma_bf16(acc[mt][nt], a[mt], bf[nt]);
    }
}

__device__ __forceinline__ void mma_store(float* __restrict__ dst, float (&acc)[4][2][4])
{
    const int lane = threadIdx.x & 31;
    const int wid  = threadIdx.x >> 5;
    const int wm = wid & 1, wn = wid >> 1;
    const int r = lane >> 2, cc = (lane & 3) * 2;
#pragma unroll
    for (int mt = 0; mt < 4; mt++)
#pragma unroll
        for (int nt = 0; nt < 2; nt++) {
            int j = wm * 64 + mt * 16 + r;
            int b = wn * 16 + nt * 8 + cc;
            *(float2*)(dst + j * B + b)       = make_float2(acc[mt][nt][0], acc[mt][nt][1]);
            *(float2*)(dst + (j + 8) * B + b) = make_float2(acc[mt][nt][2], acc[mt][nt][3]);
        }
}

__device__ __forceinline__ void acc_zero(float (&acc)[4][2][4])
{
#pragma unroll
    for (int mt = 0; mt < 4; mt++)
#pragma unroll
        for (int nt = 0; nt < 2; nt++)
#pragma unroll
            for (int u = 0; u < 4; u++) acc[mt][nt][u] = 0.f;
}

// Pipelined multi-chunk GEMM. Pre-condition: group G0 = A(chunk0) already
// issued+committed. Issues B0 (G1) and A1+B1 (G2), then runs the 2-stage ring.
template <int N>
__device__ __forceinline__ void mma_pipeline(unsigned sm0,
                                             const __nv_bfloat16* const (&Ap)[N],
                                             const __nv_bfloat16* const (&Bp)[N],
                                             float* __restrict__ dst)
{
    fillB_async(sm0 + B_OFF, Bp[0]); CP_COMMIT();                       // G1
    if (N > 1) {
        fillA_async(sm0 + STAGE_BYTES + A_OFF, Ap[1]);
        fillB_async(sm0 + STAGE_BYTES + B_OFF, Bp[1]); CP_COMMIT();     // G2
    }
    float acc[4][2][4];
    acc_zero(acc);
#pragma unroll
    for (int i = 0; i < N; i++) {
        if (i + 1 < N) { CP_WAIT(1); } else { CP_WAIT(0); }
        __syncthreads();
        unsigned st = sm0 + (i & 1) * STAGE_BYTES;
        mma_chunk(st + A_OFF, st + B_OFF, acc);
        __syncthreads();
        if (i + 2 < N) {
            unsigned st2 = sm0 + ((i + 2) & 1) * STAGE_BYTES;
            fillA_async(st2 + A_OFF, Ap[i + 2]);
            fillB_async(st2 + B_OFF, Bp[i + 2]); CP_COMMIT();
        }
    }
    mma_store(dst, acc);
}

// ---------------------------------------------------------------------------
__global__ void init_kernel()
{
    if (threadIdx.x == 0) { g_bar_cnt = 0u; g_bar_gen = 0u; }
}

// bf16x3 split: dst[i], dst[n+i], dst[2n+i]
__global__ void split_kernel(const float* __restrict__ src,
                             __nv_bfloat16* __restrict__ dst, int n)
{
    int i = blockIdx.x * 256 + threadIdx.x;
    if (i < n) {
        float w = src[i];
        __nv_bfloat16 h0 = __float2bfloat16(w);
        float r1 = w - __bfloat162float(h0);
        __nv_bfloat16 h1 = __float2bfloat16(r1);
        float r2 = r1 - __bfloat162float(h1);
        __nv_bfloat16 h2 = __float2bfloat16(r2);
        dst[i]         = h0;
        dst[n + i]     = h1;
        dst[2 * n + i] = h2;
    }
}

// 32x32 tiled transpose: out[x*R + y] = in[y*C + x]
__global__ void transpose32(const float* __restrict__ in, float* __restrict__ out,
                            int R, int C)
{
    __shared__ float tile[32][33];
    int cb = blockIdx.x * 32;
    int rb = blockIdx.y * 32;
    int x = cb + threadIdx.x;
#pragma unroll
    for (int i = threadIdx.y; i < 32; i += 8) {
        int y = rb + i;
        if (y < R && x < C) tile[i][threadIdx.x] = in[(long)y * C + x];
    }
    __syncthreads();
    int xo = rb + threadIdx.x;
#pragma unroll
    for (int i = threadIdx.y; i < 32; i += 8) {
        int yo = cb + i;
        if (yo < C && xo < R) out[(long)yo * R + xo] = tile[threadIdx.x][i];
    }
}

// ---------------------------------------------------------------------------
// fp32 tile GEMM (u_kernel only)
// ---------------------------------------------------------------------------
__device__ __forceinline__ void mm_compute_f32(const float* __restrict__ sSh,
                                               const float* __restrict__ wSh,
                                               float (&acc)[8][4])
{
    const int bq = threadIdx.x & 15;
    const int jq = threadIdx.x >> 4;
    const float4* s4 = (const float4*)sSh;
    const float4* w4 = (const float4*)wSh;
#pragma unroll 8
    for (int k = 0; k < 64; k++) {
        float4 sv = s4[k * 16 + bq];
        float4 w0 = w4[k * 32 + jq * 2];
        float4 w1 = w4[k * 32 + jq * 2 + 1];
        float sb[4] = { sv.x, sv.y, sv.z, sv.w };
        float wj[8] = { w0.x, w0.y, w0.z, w0.w, w1.x, w1.y, w1.z, w1.w };
#pragma unroll
        for (int jj = 0; jj < 8; jj++)
#pragma unroll
            for (int bb = 0; bb < 4; bb++)
                acc[jj][bb] = fmaf(wj[jj], sb[bb], acc[jj][bb]);
    }
}

__global__ void __launch_bounds__(NTHR, 2) u_kernel(const float* __restrict__ bin,
                                                    const float* __restrict__ bh1)
{
    __shared__ float sSh[64 * 64];
    __shared__ float wSh[64 * 128];
    const int t  = blockIdx.x >> 3;
    const int jt = blockIdx.x & 7;
    const int tid = threadIdx.x;

    float acc[8][4];
#pragma unroll
    for (int jj = 0; jj < 8; jj++)
#pragma unroll
        for (int bb = 0; bb < 4; bb++) acc[jj][bb] = 0.f;

    for (int kc = 0; kc < 8; kc++) {
        const float* S  = g_xT + (size_t)(t * DIN + kc * 64) * B;
        const float* Wp = g_WT_in + (size_t)kc * 64 * H1 + jt * 128;
        __syncthreads();
#pragma unroll
        for (int i = 0; i < 4; i++) {
            int idx = tid + i * 256;
            int k = idx >> 4, cc = (idx & 15) << 2;
            *(float4*)(sSh + k * 64 + cc) = __ldg((const float4*)(S + k * 64 + cc));
        }
#pragma unroll
        for (int i = 0; i < 8; i++) {
            int idx = tid + i * 256;
            int k = idx >> 5, cc = (idx & 31) << 2;
            *(float4*)(wSh + k * 128 + cc) = __ldg((const float4*)(Wp + (size_t)k * H1 + cc));
        }
        __syncthreads();
        mm_compute_f32(sSh, wSh, acc);
    }

    const int bq = tid & 15;
    const int jq = tid >> 4;
#pragma unroll
    for (int jj = 0; jj < 8; jj++) {
        int j = jt * 128 + jq * 8 + jj;
        float bias = __ldg(bin + j) + __ldg(bh1 + j);
        float4 o = make_float4(acc[jj][0] + bias, acc[jj][1] + bias,
                               acc[jj][2] + bias, acc[jj][3] + bias);
        *(float4*)(g_U + (size_t)t * (H1 * B) + j * B + bq * 4) = o;
    }
}

// ---------------------------------------------------------------------------
// Persistent recurrent kernel. 48KB dynamic smem (2 x 24KB stages).
// P1 (144 CTAs, 6 chunks of 64k: 3 splits x 2 sub-k):
//    jt 0-7 : W_h1  x s1 -> PA ; jt 8-15: W_h2 x s2 -> PBh2 ; jt 16-17: W_out x s2 -> PC
// P2: reduce PA + U -> LIF1 -> sT1 ; reduce PC -> acc
// P3 (128 CTAs, 3 chunks): W_12 x s1 -> PB12
// P4: reduce PBh2 + PB12 + biases -> LIF2 -> sT2
// Weight chunk-0 fills issued behind the preceding barrier.
// ---------------------------------------------------------------------------
__global__ void __launch_bounds__(NTHR, 1) srnn_kernel(const float* __restrict__ b12,
                                                       const float* __restrict__ bh2,
                                                       const float* __restrict__ bout,
                                                       float* __restrict__ dout)
{
    extern __shared__ char dsm[];
    const unsigned sm0 = smem_u32(dsm);

    const int c    = blockIdx.x;
    const int tid  = threadIdx.x;
    const int gtid = c * NTHR + tid;

    // ---- P1 chunk descriptors ----
    const bool p1_act = (c < 144);
    const __nv_bfloat16* p1A[6];
    const __nv_bfloat16* p1B[6];
    float* p1_dst = nullptr;
    if (p1_act) {
        int jt = c >> 3, slab = c & 7;
        const __nv_bfloat16* mat;
        size_t Jsz;
        const __nv_bfloat16* bsrc;
        int jloc;
        if (jt < 8)       { mat = g_Wh1s;  Jsz = (size_t)H1 * KDIM;   bsrc = g_sT1; jloc = jt;
                            p1_dst = g_PA   + slab * (H1 * B)   + jloc * 128 * B; }
        else if (jt < 16) { mat = g_Wh2s;  Jsz = (size_t)H2 * KDIM;   bsrc = g_sT2; jloc = jt - 8;
                            p1_dst = g_PBh2 + slab * (H2 * B)   + jloc * 128 * B; }
        else              { mat = g_Wouts; Jsz = (size_t)DOUT * KDIM; bsrc = g_sT2; jloc = jt - 16;
                            p1_dst = g_PC   + slab * (DOUT * B) + jloc * 128 * B; }
#pragma unroll
        for (int c6 = 0; c6 < 6; c6++) {
            int split = c6 >> 1;
            int kofs  = slab * 128 + (c6 & 1) * 64;
            p1A[c6] = mat + (size_t)split * Jsz + (size_t)jloc * 128 * KDIM + kofs;
            p1B[c6] = bsrc + kofs;
        }
    }
    // ---- P3 chunk descriptors ----
    const bool p3_act = (c < 128);
    const __nv_bfloat16* p3A[3];
    const __nv_bfloat16* p3B[3];
    float* p3_dst = nullptr;
    if (p3_act) {
        int jt = c >> 4, slab = c & 15;
        int kofs = slab * 64;
#pragma unroll
        for (int c3 = 0; c3 < 3; c3++) {
            p3A[c3] = g_W12s + (size_t)c3 * H2 * KDIM + (size_t)jt * 128 * KDIM + kofs;
            p3B[c3] = g_sT1 + kofs;
        }
        p3_dst = g_PB12 + slab * (H2 * B) + jt * 128 * B;
    }

    // ---- zero recurrent state ----
    {
        unsigned z2 = 0;  // two bf16 zeros
        for (int i = gtid; i < (B * H1) / 2; i += GSTRIDE) ((unsigned*)g_sT1)[i] = z2;
        for (int i = gtid; i < (B * H2) / 2; i += GSTRIDE) ((unsigned*)g_sT2)[i] = z2;
    }
    for (int i = gtid; i < H1 * B;   i += GSTRIDE) g_v1[i]  = 0.f;
    for (int i = gtid; i < H2 * B;   i += GSTRIDE) g_v2[i]  = 0.f;
    for (int i = gtid; i < DOUT * B; i += GSTRIDE) g_acc[i] = 0.f;

    // prefetch P1 chunk-0 weights behind the first barrier (G0)
    if (p1_act) { fillA_async(sm0 + A_OFF, p1A[0]); CP_COMMIT(); }
    grid_sync();

    for (int t = 0; t < T; t++) {
        // ---- Phase 1 ----
        if (p1_act) mma_pipeline<6>(sm0, p1A, p1B, p1_dst);
        grid_sync();

        // ---- Phase 2: reduce PA + U -> LIF1 -> sT1 ; reduce PC -> acc ----
        {
            const int i4 = gtid;
            if (i4 < (H1 * B) / 4) {
                const float4* Ut4 = (const float4*)(g_U + (size_t)t * (H1 * B));
                float4 sum = __ldg(Ut4 + i4);
#pragma unroll
                for (int kc = 0; kc < 8; kc++) {
                    float4 p = __ldcg((const float4*)g_PA + kc * (H1 * B / 4) + i4);
                    sum.x += p.x; sum.y += p.y; sum.z += p.z; sum.w += p.w;
                }
                float4 v = *((float4*)g_v1 + i4);
                float4 s;
                v.x = 0.9f * v.x + sum.x; s.x = (v.x >= 1.f) ? 1.f : 0.f; v.x -= s.x;
                v.y = 0.9f * v.y + sum.y; s.y = (v.y >= 1.f) ? 1.f : 0.f; v.y -= s.y;
                v.z = 0.9f * v.z + sum.z; s.z = (v.z >= 1.f) ? 1.f : 0.f; v.z -= s.z;
                v.w = 0.9f * v.w + sum.w; s.w = (v.w >= 1.f) ? 1.f : 0.f; v.w -= s.w;
                *((float4*)g_v1 + i4) = v;
                int j  = i4 >> 4;
                int b0 = (i4 & 15) * 4;
                g_sT1[(b0 + 0) * H1 + j] = __float2bfloat16(s.x);
                g_sT1[(b0 + 1) * H1 + j] = __float2bfloat16(s.y);
                g_sT1[(b0 + 2) * H1 + j] = __float2bfloat16(s.z);
                g_sT1[(b0 + 3) * H1 + j] = __float2bfloat16(s.w);
            }
            if (i4 < (DOUT * B) / 4) {
                float4 sum = make_float4(0.f, 0.f, 0.f, 0.f);
#pragma unroll
                for (int kc = 0; kc < 8; kc++) {
                    float4 p = __ldcg((const float4*)g_PC + kc * (DOUT * B / 4) + i4);
                    sum.x += p.x; sum.y += p.y; sum.z += p.z; sum.w += p.w;
                }
                float4 a = *((float4*)g_acc + i4);
                a.x += sum.x; a.y += sum.y; a.z += sum.z; a.w += sum.w;
                *((float4*)g_acc + i4) = a;
            }
        }
        // prefetch P3 chunk-0 weights behind the barrier
        if (p3_act) { fillA_async(sm0 + A_OFF, p3A[0]); CP_COMMIT(); }
        grid_sync();

        // ---- Phase 3 ----
        if (p3_act) mma_pipeline<3>(sm0, p3A, p3B, p3_dst);
        grid_sync();

        // ---- Phase 4: reduce + biases -> LIF2 -> sT2 ----
        {
            const int i4 = gtid;
            if (i4 < (H2 * B) / 4) {
                int j = i4 >> 4;
                float bias = __ldg(b12 + j) + __ldg(bh2 + j);
                float4 sum = make_float4(bias, bias, bias, bias);
#pragma unroll
                for (int kc = 0; kc < 8; kc++) {
                    float4 p = __ldcg((const float4*)g_PBh2 + kc * (H2 * B / 4) + i4);
                    sum.x += p.x; sum.y += p.y; sum.z += p.z; sum.w += p.w;
                }
#pragma unroll
                for (int kc = 0; kc < 16; kc++) {
                    float4 p = __ldcg((const float4*)g_PB12 + kc * (H2 * B / 4) + i4);
                    sum.x += p.x; sum.y += p.y; sum.z += p.z; sum.w += p.w;
                }
                float4 v = *((float4*)g_v2 + i4);
                float4 s;
                v.x = 0.9f * v.x + sum.x; s.x = (v.x >= 1.f) ? 1.f : 0.f; v.x -= s.x;
                v.y = 0.9f * v.y + sum.y; s.y = (v.y >= 1.f) ? 1.f : 0.f; v.y -= s.y;
                v.z = 0.9f * v.z + sum.z; s.z = (v.z >= 1.f) ? 1.f : 0.f; v.z -= s.z;
                v.w = 0.9f * v.w + sum.w; s.w = (v.w >= 1.f) ? 1.f : 0.f; v.w -= s.w;
                *((float4*)g_v2 + i4) = v;
                int b0 = (i4 & 15) * 4;
                g_sT2[(b0 + 0) * H2 + j] = __float2bfloat16(s.x);
                g_sT2[(b0 + 1) * H2 + j] = __float2bfloat16(s.y);
                g_sT2[(b0 + 2) * H2 + j] = __float2bfloat16(s.z);
                g_sT2[(b0 + 3) * H2 + j] = __float2bfloat16(s.w);
            }
        }
        // prefetch next step's P1 chunk-0 weights behind the barrier
        if (t + 1 < T && p1_act) { fillA_async(sm0 + A_OFF, p1A[0]); CP_COMMIT(); }
        grid_sync();
    }

    // ---- Final readout contribution from s2_{T-1} (16 CTAs) ----
    if (c < 16) {
        int jloc = c >> 3, slab = c & 7;
        const __nv_bfloat16* Ap[6];
        const __nv_bfloat16* Bp[6];
#pragma unroll
        for (int c6 = 0; c6 < 6; c6++) {
            int split = c6 >> 1;
            int kofs  = slab * 128 + (c6 & 1) * 64;
            Ap[c6] = g_Wouts + (size_t)split * DOUT * KDIM + (size_t)jloc * 128 * KDIM + kofs;
            Bp[c6] = g_sT2 + kofs;
        }
        fillA_async(sm0 + A_OFF, Ap[0]); CP_COMMIT();   // G0
        mma_pipeline<6>(sm0, Ap, Bp, g_PC + slab * (DOUT * B) + jloc * 128 * B);
    }
    grid_sync();

    for (int i = gtid; i < DOUT * B; i += GSTRIDE) {
        float sum = 0.f;
#pragma unroll
        for (int kc = 0; kc < 8; kc++) sum += __ldcg(g_PC + kc * (DOUT * B) + i);
        int j = i >> 6;
        int b = i & 63;
        dout[b * DOUT + j] = __ldcg(g_acc + i) + sum + 512.0f * __ldg(bout + j);
    }
}

// ---------------------------------------------------------------------------
// Host launcher
// ---------------------------------------------------------------------------
extern "C" void kernel_launch(void* const* d_in, const int* in_sizes, int n_in,
                              void* d_out, int out_size)
{
    const float* x     = (const float*)d_in[0];
    const float* W_in  = (const float*)d_in[1];
    const float* b_in  = (const float*)d_in[2];
    const float* W_h1  = (const float*)d_in[3];
    const float* b_h1  = (const float*)d_in[4];
    const float* W_12  = (const float*)d_in[5];
    const float* b_12  = (const float*)d_in[6];
    const float* W_h2  = (const float*)d_in[7];
    const float* b_h2  = (const float*)d_in[8];
    const float* W_out = (const float*)d_in[9];
    const float* b_out = (const float*)d_in[10];
    float* out = (float*)d_out;

    float *p_xT, *p_WT_in;
    __nv_bfloat16 *p_Wh1s, *p_Wh2s, *p_W12s, *p_Wouts;
    cudaGetSymbolAddress((void**)&p_xT,    g_xT);
    cudaGetSymbolAddress((void**)&p_WT_in, g_WT_in);
    cudaGetSymbolAddress((void**)&p_Wh1s,  g_Wh1s);
    cudaGetSymbolAddress((void**)&p_Wh2s,  g_Wh2s);
    cudaGetSymbolAddress((void**)&p_W12s,  g_W12s);
    cudaGetSymbolAddress((void**)&p_Wouts, g_Wouts);

    cudaFuncSetAttribute(srnn_kernel, cudaFuncAttributeMaxDynamicSharedMemorySize,
                         2 * STAGE_BYTES);

    init_kernel<<<1, 32>>>();

    dim3 tb(32, 8);
    // x [B, T*DIN] -> xT [T*DIN, B]
    transpose32<<<dim3(8192, 2), tb>>>(x, p_xT, 64, T * DIN);
    // W_in [H1, DIN] -> WT_in [DIN, H1]
    transpose32<<<dim3(16, 32), tb>>>(W_in, p_WT_in, H1, DIN);

    // bf16x3 weight splits (weights already [j][k] row-major)
    split_kernel<<<(H1 * KDIM + 255) / 256, 256>>>(W_h1, p_Wh1s, H1 * KDIM);
    split_kernel<<<(H2 * KDIM + 255) / 256, 256>>>(W_h2, p_Wh2s, H2 * KDIM);
    split_kernel<<<(H2 * KDIM + 255) / 256, 256>>>(W_12, p_W12s, H2 * KDIM);
    split_kernel<<<(DOUT * KDIM + 255) / 256, 256>>>(W_out, p_Wouts, DOUT * KDIM);

    // Precompute U for all timesteps (fp32)
    u_kernel<<<T * 8, NTHR>>>(b_in, b_h1);

    // Persistent sequential scan
    srnn_kernel<<<NCTA, NTHR, 2 * STAGE_BYTES>>>(b_12, b_h2, b_out, out);
}